// round 2
// baseline (speedup 1.0000x reference)
#include <cuda_runtime.h>
#include <cuda_bf16.h>

#define BATCH 16
#define N 256
#define DIM 128

// Scratch (device globals: allocation-free per harness rules)
__device__ float  g_dist[BATCH * N * N];   // 4 MB, fp32 pairwise distances
__device__ double g_bsum[BATCH];           // per-batch matched sums

// ---------------------------------------------------------------------------
// Kernel A: pairwise L2 distances. One block computes a 16x16 tile of dist.
// grid = (16 col-tiles, 16 row-tiles, 16 batches), 256 threads.
// ---------------------------------------------------------------------------
__global__ __launch_bounds__(256) void dist_kernel(const float* __restrict__ pred,
                                                   const float* __restrict__ tgt) {
    __shared__ float sp[16 * 132];   // 16 rows x 128 floats, padded to 132
    __shared__ float st[16 * 132];
    const int b  = blockIdx.z;
    const int rt = blockIdx.y;
    const int ct = blockIdx.x;
    const int tid = threadIdx.x;

    const float4* p4 = (const float4*)(pred + (size_t)(b * N + rt * 16) * DIM);
    const float4* t4 = (const float4*)(tgt  + (size_t)(b * N + ct * 16) * DIM);
    for (int idx = tid; idx < 512; idx += 256) {     // 16*128/4 = 512 float4
        int r = idx >> 5, c = idx & 31;
        *(float4*)&sp[r * 132 + c * 4] = p4[idx];
        *(float4*)&st[r * 132 + c * 4] = t4[idx];
    }
    __syncthreads();

    const int ti = tid >> 4;   // 0..15 row within tile
    const int tj = tid & 15;   // 0..15 col within tile
    float acc = 0.f;
#pragma unroll
    for (int d4 = 0; d4 < 32; ++d4) {
        float4 a = *(const float4*)&sp[ti * 132 + d4 * 4];
        float4 c = *(const float4*)&st[tj * 132 + d4 * 4];
        float dx = a.x - c.x, dy = a.y - c.y, dz = a.z - c.z, dw = a.w - c.w;
        acc += dx * dx + dy * dy + dz * dz + dw * dw;
    }
    g_dist[((size_t)b << 16) + (size_t)(rt * 16 + ti) * N + (ct * 16 + tj)] = sqrtf(acc);
}

// ---------------------------------------------------------------------------
// Kernel B: per-batch Jonker-Volgenant LSA on u16-quantized costs.
// One block per batch, 256 threads. Phase 1: quantize dist -> smem u16.
// Phase 2 (warp 0 only): Dijkstra with potentials, deferred dual updates.
//   Each lane owns 8 consecutive columns; D/v/used/pi live in registers.
// Phase 3: all threads gather matched fp32 distances, deterministic reduce.
// ---------------------------------------------------------------------------
#define QSCALE 2048.0f
#define INF_D  0x3F000000
#define INF_M  0x7F000000

// dynamic smem layout (bytes)
#define OFF_COST 0                      // u16[65536]           = 131072
#define OFF_U    131072                 // int[257]             = 1028
#define OFF_P    (131072 + 1028)        // u16[257]             = 514
#define OFF_WAY  (131072 + 1028 + 514)  // u16[257]             = 514
#define OFF_SRED (131072 + 1028 + 514 + 514)  // = 133128, 8-aligned; double[8]
#define SMEM_B   (OFF_SRED + 64)

extern __shared__ char s_raw[];

__global__ __launch_bounds__(256) void hungarian_kernel() {
    const int b   = blockIdx.x;
    const int tid = threadIdx.x;

    unsigned short* cost = (unsigned short*)(s_raw + OFF_COST);
    int*            u_   = (int*)(s_raw + OFF_U);
    unsigned short* p_   = (unsigned short*)(s_raw + OFF_P);
    unsigned short* way_ = (unsigned short*)(s_raw + OFF_WAY);
    double*         sred = (double*)(s_raw + OFF_SRED);

    // ---- Phase 1: quantize the fp32 distance block into shared u16 ----
    const float4* dsrc = (const float4*)(g_dist + ((size_t)b << 16));
    for (int idx = tid; idx < (N * N) / 4; idx += 256) {
        float4 d = dsrc[idx];
        int q0 = __float2int_rn(d.x * QSCALE); q0 = q0 > 65535 ? 65535 : q0;
        int q1 = __float2int_rn(d.y * QSCALE); q1 = q1 > 65535 ? 65535 : q1;
        int q2 = __float2int_rn(d.z * QSCALE); q2 = q2 > 65535 ? 65535 : q2;
        int q3 = __float2int_rn(d.w * QSCALE); q3 = q3 > 65535 ? 65535 : q3;
        ((ushort4*)cost)[idx] = make_ushort4((unsigned short)q0, (unsigned short)q1,
                                             (unsigned short)q2, (unsigned short)q3);
    }
    for (int i = tid; i < N + 1; i += 256) { u_[i] = 0; p_[i] = 0; }
    __syncthreads();

    // ---- Phase 2: warp 0 runs the LSA ----
    if (tid < 32) {
        const unsigned FULL = 0xffffffffu;
        const int lane = tid;
        int vreg[8], Dreg[8], pireg[8];
#pragma unroll
        for (int k = 0; k < 8; ++k) vreg[k] = 0;

        for (int i = 1; i <= N; ++i) {
            unsigned usedmask = 0;
#pragma unroll
            for (int k = 0; k < 8; ++k) Dreg[k] = INF_D;
            if (lane == 0) p_[0] = (unsigned short)i;

            int S = 0;
            int i0 = i;      // current row being relaxed (u[i]=0 for the new row)
            int j0 = 0;      // virtual start column
            int jfinal;

            while (true) {
                const int u0 = u_[i0];
                const uint4 cc = ((const uint4*)(cost + ((i0 - 1) << 8)))[lane];
                unsigned cw[4] = {cc.x, cc.y, cc.z, cc.w};
#pragma unroll
                for (int k = 0; k < 8; ++k) {
                    if (!((usedmask >> k) & 1u)) {
                        int c = (int)((cw[k >> 1] >> ((k & 1) * 16)) & 0xFFFFu);
                        int cand = S + c - u0 - vreg[k];
                        if (cand < Dreg[k]) {
                            Dreg[k] = cand;
                            way_[(lane << 3) + k + 1] = (unsigned short)j0;
                        }
                    }
                }
                // min over free columns
                int mn = INF_M;
#pragma unroll
                for (int k = 0; k < 8; ++k)
                    if (!((usedmask >> k) & 1u) && Dreg[k] < mn) mn = Dreg[k];
                const int g = __reduce_min_sync(FULL, mn);
                // lowest column achieving the min
                int localj = 0x7FFFFFFF;
#pragma unroll
                for (int k = 0; k < 8; ++k)
                    if (localj == 0x7FFFFFFF && !((usedmask >> k) & 1u) && Dreg[k] == g)
                        localj = (lane << 3) + k + 1;
                const unsigned bal = __ballot_sync(FULL, localj != 0x7FFFFFFF);
                const int src = __ffs(bal) - 1;
                const int j1  = __shfl_sync(FULL, localj, src);
                S = g;
                const int pj1 = p_[j1];
                if (pj1 == 0) { jfinal = j1; break; }
                // freeze j1 on its owner lane (static-index predicated loop)
#pragma unroll
                for (int k = 0; k < 8; ++k)
                    if (((lane << 3) + k + 1) == j1) { usedmask |= (1u << k); pireg[k] = pj1; }
                i0 = pj1;
                j0 = j1;
            }

            const int mu = S;
            __syncwarp();                 // way_ writes visible to lane 0
            if (lane == 0) {
                int jj = jfinal;          // augment along the alternating path
                while (jj != 0) {
                    int jp = way_[jj];
                    p_[jj] = p_[jp];
                    jj = jp;
                }
                u_[i] += mu;              // virtual column 0 (D=0)
            }
            // deferred dual updates for columns frozen this round
#pragma unroll
            for (int k = 0; k < 8; ++k)
                if ((usedmask >> k) & 1u) {
                    int adj = mu - Dreg[k];
                    vreg[k] -= adj;
                    u_[pireg[k]] += adj;  // distinct rows: race-free
                }
            __syncwarp();
        }
    }
    __syncthreads();

    // ---- Phase 3: gather matched fp32 distances, deterministic block sum ----
    {
        const int j   = tid + 1;
        const int row = p_[j];
        float val = g_dist[((size_t)b << 16) + (size_t)(row - 1) * N + (j - 1)];
        double d = (double)val;
#pragma unroll
        for (int off = 16; off > 0; off >>= 1)
            d += __shfl_down_sync(0xffffffffu, d, off);
        if ((tid & 31) == 0) sred[tid >> 5] = d;
        __syncthreads();
        if (tid == 0) {
            double t = 0.0;
#pragma unroll
            for (int w = 0; w < 8; ++w) t += sred[w];   // fixed order
            g_bsum[b] = t;
        }
    }
}

// ---------------------------------------------------------------------------
// Kernel C: deterministic final reduce + mean
// ---------------------------------------------------------------------------
__global__ void finalize_kernel(float* __restrict__ out) {
    double t = 0.0;
#pragma unroll
    for (int b = 0; b < BATCH; ++b) t += g_bsum[b];
    out[0] = (float)(t / (double)(BATCH * N));
}

// ---------------------------------------------------------------------------
extern "C" void kernel_launch(void* const* d_in, const int* in_sizes, int n_in,
                              void* d_out, int out_size) {
    const float* pred = (const float*)d_in[0];
    const float* tgt  = (const float*)d_in[1];
    float* out = (float*)d_out;

    cudaFuncSetAttribute(hungarian_kernel,
                         cudaFuncAttributeMaxDynamicSharedMemorySize, SMEM_B);

    dist_kernel<<<dim3(16, 16, 16), 256>>>(pred, tgt);
    hungarian_kernel<<<BATCH, 256, SMEM_B>>>();
    finalize_kernel<<<1, 1>>>(out);
}

// round 3
// speedup vs baseline: 5.2993x; 5.2993x over previous
#include <cuda_runtime.h>
#include <cuda_bf16.h>

#define BATCH 16
#define N 256
#define DIM 128

// Scratch (device globals: allocation-free per harness rules)
__device__ float  g_dist[BATCH * N * N];   // 4 MB, fp32 pairwise distances
__device__ double g_bsum[BATCH];           // per-batch matched sums

// ---------------------------------------------------------------------------
// Kernel A: pairwise L2 distances. One block computes a 16x16 tile of dist.
// ---------------------------------------------------------------------------
__global__ __launch_bounds__(256) void dist_kernel(const float* __restrict__ pred,
                                                   const float* __restrict__ tgt) {
    __shared__ float sp[16 * 132];
    __shared__ float st[16 * 132];
    const int b  = blockIdx.z;
    const int rt = blockIdx.y;
    const int ct = blockIdx.x;
    const int tid = threadIdx.x;

    const float4* p4 = (const float4*)(pred + (size_t)(b * N + rt * 16) * DIM);
    const float4* t4 = (const float4*)(tgt  + (size_t)(b * N + ct * 16) * DIM);
    for (int idx = tid; idx < 512; idx += 256) {
        int r = idx >> 5, c = idx & 31;
        *(float4*)&sp[r * 132 + c * 4] = p4[idx];
        *(float4*)&st[r * 132 + c * 4] = t4[idx];
    }
    __syncthreads();

    const int ti = tid >> 4;
    const int tj = tid & 15;
    float acc = 0.f;
#pragma unroll
    for (int d4 = 0; d4 < 32; ++d4) {
        float4 a = *(const float4*)&sp[ti * 132 + d4 * 4];
        float4 c = *(const float4*)&st[tj * 132 + d4 * 4];
        float dx = a.x - c.x, dy = a.y - c.y, dz = a.z - c.z, dw = a.w - c.w;
        acc += dx * dx + dy * dy + dz * dz + dw * dw;
    }
    g_dist[((size_t)b << 16) + (size_t)(rt * 16 + ti) * N + (ct * 16 + tj)] = sqrtf(acc);
}

// ---------------------------------------------------------------------------
// Kernel B: per-batch Jonker-Volgenant LSA on u16-quantized costs.
//   Column-reduction init (v = per-column min + greedy pre-assign) then
//   warp-0 Dijkstra with (D<<9|j)-packed redux-min and sentinel-masked
//   frozen columns. Each lane owns 8 consecutive columns in registers.
// ---------------------------------------------------------------------------
#define QSCALE 2048.0f

// dynamic smem layout (bytes)
#define OFF_COST 0                       // u16[65536] = 131072
#define OFF_U    131072                  // int[257]   = 1028  -> 132100
#define OFF_P    132100                  // u16[257]   = 514   -> 132614
#define OFF_WAY  132624                  // u16[256]   = 512   -> 133136 (16-aligned)
#define OFF_RMIN 133136                  // u16[256]   = 512   -> 133648 (16-aligned)
#define OFF_ROWT 133648                  // u32[8]     = 32    -> 133680
#define OFF_SRED 133680                  // double[8]  = 64    -> 133744
#define SMEM_B   133744

extern __shared__ char s_raw[];

__global__ __launch_bounds__(256) void hungarian_kernel() {
    const int b   = blockIdx.x;
    const int tid = threadIdx.x;

    unsigned short* cost  = (unsigned short*)(s_raw + OFF_COST);
    int*            u_    = (int*)(s_raw + OFF_U);
    unsigned short* p_    = (unsigned short*)(s_raw + OFF_P);
    unsigned short* way0_ = (unsigned short*)(s_raw + OFF_WAY);
    unsigned short* srmin = (unsigned short*)(s_raw + OFF_RMIN);
    unsigned*       srowt = (unsigned*)(s_raw + OFF_ROWT);
    double*         sred  = (double*)(s_raw + OFF_SRED);

    // ---- Phase 1: quantize fp32 distances into shared u16, init duals ----
    const float4* dsrc = (const float4*)(g_dist + ((size_t)b << 16));
    for (int idx = tid; idx < (N * N) / 4; idx += 256) {
        float4 d = dsrc[idx];
        int q0 = __float2int_rn(d.x * QSCALE); q0 = q0 > 65535 ? 65535 : q0;
        int q1 = __float2int_rn(d.y * QSCALE); q1 = q1 > 65535 ? 65535 : q1;
        int q2 = __float2int_rn(d.z * QSCALE); q2 = q2 > 65535 ? 65535 : q2;
        int q3 = __float2int_rn(d.w * QSCALE); q3 = q3 > 65535 ? 65535 : q3;
        ((ushort4*)cost)[idx] = make_ushort4((unsigned short)q0, (unsigned short)q1,
                                             (unsigned short)q2, (unsigned short)q3);
    }
    for (int i = tid; i < N + 1; i += 256) { u_[i] = 0; p_[i] = 0; }
    __syncthreads();

    // ---- Phase 2: warp 0 runs the LSA ----
    if (tid < 32) {
        const unsigned FULL = 0xffffffffu;
        const int lane = tid;

        // Column reduction: v[j] = min_i cost[i][j], rmin[j] = first argmin row.
        unsigned vmin[8]; int rmin[8];
#pragma unroll
        for (int k = 0; k < 8; ++k) { vmin[k] = 0xFFFFFFFFu; rmin[k] = 0; }
        for (int r = 0; r < N; ++r) {
            uint4 cc = ((const uint4*)(cost + (r << 8)))[lane];
            unsigned wv[4] = {cc.x, cc.y, cc.z, cc.w};
#pragma unroll
            for (int k = 0; k < 8; ++k) {
                unsigned c = (wv[k >> 1] >> ((k & 1) * 16)) & 0xFFFFu;
                if (c < vmin[k]) { vmin[k] = c; rmin[k] = r; }
            }
        }
        {
            unsigned a0 = (unsigned)rmin[0] | ((unsigned)rmin[1] << 16);
            unsigned a1 = (unsigned)rmin[2] | ((unsigned)rmin[3] << 16);
            unsigned a2 = (unsigned)rmin[4] | ((unsigned)rmin[5] << 16);
            unsigned a3 = (unsigned)rmin[6] | ((unsigned)rmin[7] << 16);
            ((uint4*)srmin)[lane] = make_uint4(a0, a1, a2, a3);
        }
        if (lane < 8) srowt[lane] = 0u;
        __syncwarp();
        // Greedy pre-assignment: column j -> rmin[j] if that row is still free.
        if (lane == 0) {
            for (int j = 0; j < N; ++j) {
                int r = srmin[j];
                unsigned wd = srowt[r >> 5];
                if (!((wd >> (r & 31)) & 1u)) {
                    srowt[r >> 5] = wd | (1u << (r & 31));
                    p_[j + 1] = (unsigned short)(r + 1);
                }
            }
        }
        __syncwarp();

        int vreg[8];
#pragma unroll
        for (int k = 0; k < 8; ++k) vreg[k] = (int)vmin[k];
        unsigned rt[8];
#pragma unroll
        for (int w = 0; w < 8; ++w) rt[w] = srowt[w];

        // Dijkstra for each unassigned row (uniform across the warp).
        for (int w = 0; w < 8; ++w) {
            unsigned freeb = ~rt[w];
            while (freeb) {
                const int bz = __ffs(freeb) - 1;
                freeb &= freeb - 1;
                const int i = w * 32 + bz + 1;

                unsigned Dp[8], offk[8], fz = 0;
                int wayreg[8], wlock[8], Sfz[8], pifz[8];
#pragma unroll
                for (int k = 0; k < 8; ++k) {
                    Dp[k] = 0xFFFFFFFFu;
                    wayreg[k] = 0;
                    offk[k] = (unsigned)((lane << 3) + k + 1) - (((unsigned)vreg[k]) << 9);
                }
                if (lane == 0) p_[0] = (unsigned short)i;

                int S = 0, i0 = i, j0 = 0, jfinal;

                while (true) {
                    const int u0 = u_[i0];
                    const uint4 cc = ((const uint4*)(cost + ((i0 - 1) << 8)))[lane];
                    int baseS = S - u0;
                    if (baseS > (1 << 21)) baseS = 1 << 21;       // overflow guard
                    const unsigned bsh = ((unsigned)baseS) << 9;
                    unsigned wv[4] = {cc.x, cc.y, cc.z, cc.w};
#pragma unroll
                    for (int k = 0; k < 8; ++k) {
                        unsigned word = wv[k >> 1];
                        unsigned csh = (k & 1) ? ((word >> 7) & 0x01FFFE00u)
                                               : ((word << 9) & 0x01FFFE00u);
                        unsigned cand = bsh + csh + offk[k];      // (D<<9)|j packed
                        if (cand < Dp[k]) { Dp[k] = cand; wayreg[k] = j0; }
                    }
                    // lane-local min tree then warp redux (frozen >= 2^31 never win)
                    unsigned m01 = Dp[0] < Dp[1] ? Dp[0] : Dp[1];
                    unsigned m23 = Dp[2] < Dp[3] ? Dp[2] : Dp[3];
                    unsigned m45 = Dp[4] < Dp[5] ? Dp[4] : Dp[5];
                    unsigned m67 = Dp[6] < Dp[7] ? Dp[6] : Dp[7];
                    unsigned ma = m01 < m23 ? m01 : m23;
                    unsigned mb = m45 < m67 ? m45 : m67;
                    const unsigned g = __reduce_min_sync(FULL, ma < mb ? ma : mb);
                    const int j1 = (int)(g & 511u);
                    S = (int)(g >> 9);
                    const int pj1 = p_[j1];
                    if (pj1 == 0) { jfinal = j1; break; }
#pragma unroll
                    for (int k = 0; k < 8; ++k)
                        if (((lane << 3) + k + 1) == j1) {
                            fz |= (1u << k);
                            Sfz[k] = S; pifz[k] = pj1;
                            wlock[k] = wayreg[k];          // snapshot predecessor
                            offk[k] += 0x80000000u;        // sentinel: never wins
                            Dp[k] = 0xFFFFFFFFu;
                        }
                    i0 = pj1; j0 = j1;
                }

                const int mu = S;
                // publish way pointers (frozen columns use freeze-time snapshot)
                {
                    unsigned wout[8];
#pragma unroll
                    for (int k = 0; k < 8; ++k)
                        wout[k] = (unsigned)(((fz >> k) & 1u) ? wlock[k] : wayreg[k]) & 0xFFFFu;
                    unsigned a0 = wout[0] | (wout[1] << 16);
                    unsigned a1 = wout[2] | (wout[3] << 16);
                    unsigned a2 = wout[4] | (wout[5] << 16);
                    unsigned a3 = wout[6] | (wout[7] << 16);
                    ((uint4*)way0_)[lane] = make_uint4(a0, a1, a2, a3);
                }
                __syncwarp();
                if (lane == 0) {
                    int jj = jfinal;
                    while (jj != 0) {
                        int jp = way0_[jj - 1];
                        p_[jj] = p_[jp];
                        jj = jp;
                    }
                    u_[i] += mu;
                }
                // deferred dual updates (distinct rows per frozen column: race-free)
#pragma unroll
                for (int k = 0; k < 8; ++k)
                    if ((fz >> k) & 1u) {
                        int adj = mu - Sfz[k];
                        vreg[k] -= adj;
                        u_[pifz[k]] += adj;
                    }
                __syncwarp();
            }
        }
    }
    __syncthreads();

    // ---- Phase 3: gather matched fp32 distances, deterministic block sum ----
    {
        const int j   = tid + 1;
        const int row = p_[j];
        float val = g_dist[((size_t)b << 16) + (size_t)(row - 1) * N + (j - 1)];
        double d = (double)val;
#pragma unroll
        for (int off = 16; off > 0; off >>= 1)
            d += __shfl_down_sync(0xffffffffu, d, off);
        if ((tid & 31) == 0) sred[tid >> 5] = d;
        __syncthreads();
        if (tid == 0) {
            double t = 0.0;
#pragma unroll
            for (int w = 0; w < 8; ++w) t += sred[w];   // fixed order
            g_bsum[b] = t;
        }
    }
}

// ---------------------------------------------------------------------------
// Kernel C: deterministic final reduce + mean
// ---------------------------------------------------------------------------
__global__ void finalize_kernel(float* __restrict__ out) {
    double t = 0.0;
#pragma unroll
    for (int b = 0; b < BATCH; ++b) t += g_bsum[b];
    out[0] = (float)(t / (double)(BATCH * N));
}

// ---------------------------------------------------------------------------
extern "C" void kernel_launch(void* const* d_in, const int* in_sizes, int n_in,
                              void* d_out, int out_size) {
    const float* pred = (const float*)d_in[0];
    const float* tgt  = (const float*)d_in[1];
    float* out = (float*)d_out;

    cudaFuncSetAttribute(hungarian_kernel,
                         cudaFuncAttributeMaxDynamicSharedMemorySize, SMEM_B);

    dist_kernel<<<dim3(16, 16, 16), 256>>>(pred, tgt);
    hungarian_kernel<<<BATCH, 256, SMEM_B>>>();
    finalize_kernel<<<1, 1>>>(out);
}